// round 12
// baseline (speedup 1.0000x reference)
#include <cuda_runtime.h>
#include <math.h>
#include <stdint.h>

#define M_TOT 16384
#define D_IN  2048
#define N_TOT 1728
#define N_PAD 1792
#define SEQ   4096
#define NKT   (D_IN / 8)      // 256 k-tiles of 8

// column offsets inside a packed Y row
#define OFF_AQ 0
#define OFF_AK 128
#define OFF_AV 160
#define OFF_BQ 192
#define OFF_BK 1216
#define OFF_BV 1472

// scratch (static device arrays: allocation-free per harness rules)
// A packed: [mt (m/16)][kt (k/8)][128 words]
__device__ float g_X[(size_t)M_TOT * D_IN];
// B packed: [nt (n/8)][kt (k/8)][64 words]
__device__ float g_W[(size_t)N_PAD * D_IN];
__device__ float g_Y[(size_t)M_TOT * N_PAD];
__device__ float g_cos[SEQ * 64];
__device__ float g_sin[SEQ * 64];

__device__ __forceinline__ float to_tf32(float x) {
    uint32_t r;
    asm("cvt.rna.tf32.f32 %0, %1;" : "=r"(r) : "f"(x));
    return __uint_as_float(r);
}

// pack X fragment-major with fully coalesced 128-bit loads & stores.
__global__ __launch_bounds__(256) void k_prep_x(const float* __restrict__ x) {
    int gid  = blockIdx.x * 256 + threadIdx.x;
    int lane = gid & 31;
    int w    = gid >> 5;               // warp id: 0..65535
    int gp   = lane & 7, ktl = lane >> 3;
    int kt   = (w & 63) * 4 + ktl;     // 0..255
    int mt   = w >> 6;                 // 0..1023
    const float* r0 = x + (size_t)(mt * 16 + gp) * D_IN + kt * 8;
    float4 a0 = *reinterpret_cast<const float4*>(r0);
    float4 a1 = *reinterpret_cast<const float4*>(r0 + 4);
    float4 b0 = *reinterpret_cast<const float4*>(r0 + 8 * D_IN);
    float4 b1 = *reinterpret_cast<const float4*>(r0 + 8 * D_IN + 4);
    a0.x = to_tf32(a0.x); a0.y = to_tf32(a0.y); a0.z = to_tf32(a0.z); a0.w = to_tf32(a0.w);
    a1.x = to_tf32(a1.x); a1.y = to_tf32(a1.y); a1.z = to_tf32(a1.z); a1.w = to_tf32(a1.w);
    b0.x = to_tf32(b0.x); b0.y = to_tf32(b0.y); b0.z = to_tf32(b0.z); b0.w = to_tf32(b0.w);
    b1.x = to_tf32(b1.x); b1.y = to_tf32(b1.y); b1.z = to_tf32(b1.z); b1.w = to_tf32(b1.w);
    float4* dst = reinterpret_cast<float4*>(
        g_X + (((size_t)mt * NKT + kt) << 7) + gp * 16);
    dst[0] = make_float4(a0.x, b0.x, a1.x, b1.x);
    dst[1] = make_float4(a0.y, b0.y, a1.y, b1.y);
    dst[2] = make_float4(a0.z, b0.z, a1.z, b1.z);
    dst[3] = make_float4(a0.w, b0.w, a1.w, b1.w);
}

// tiled transpose + pack into g_W fragment-major; pads n in [1728,1792) with 0
__global__ void k_prep_w(
    const float* __restrict__ wa_q, const float* __restrict__ wa_k,
    const float* __restrict__ wa_v, const float* __restrict__ wb_q,
    const float* __restrict__ wb_k, const float* __restrict__ wb_v) {
    __shared__ float t[32][33];
    const int n0 = blockIdx.x * 32, k0 = blockIdx.y * 32;
    const int tx = threadIdx.x, ty = threadIdx.y;
    const float* src = nullptr; int ld = 0, nb = 0;
    if      (n0 < 128)  { src = wa_q; ld = 128;  nb = 0;    }
    else if (n0 < 160)  { src = wa_k; ld = 32;   nb = 128;  }
    else if (n0 < 192)  { src = wa_v; ld = 32;   nb = 160;  }
    else if (n0 < 1216) { src = wb_q; ld = 1024; nb = 192;  }
    else if (n0 < 1472) { src = wb_k; ld = 256;  nb = 1216; }
    else if (n0 < 1728) { src = wb_v; ld = 256;  nb = 1472; }
#pragma unroll
    for (int j = 0; j < 4; j++) {
        int r = ty + 8 * j;   // k row within tile
        float v = src ? src[(size_t)(k0 + r) * ld + (n0 - nb) + tx] : 0.f;
        t[r][tx] = to_tf32(v);
    }
    __syncthreads();
#pragma unroll
    for (int j = 0; j < 4; j++) {
        int r = ty + 8 * j;   // n row within tile
        int n = n0 + r, k = k0 + tx;
        size_t lin = (((size_t)(n >> 3) * NKT + (k >> 3)) << 6)
                   + (((n & 7) * 4 + (k & 3)) << 1) + ((k >> 2) & 1);
        g_W[lin] = t[tx][r];
    }
}

__global__ __launch_bounds__(256) void k_rope() {
    int i = blockIdx.x * 256 + threadIdx.x;
    if (i >= SEQ * 64) return;
    int s = i >> 6, d = i & 63;
    float ex   = -(float)d * (1.0f / 64.0f);
    float invf = exp2f(ex * 13.28771237954945f); // log2(10000)
    float f    = (float)s * invf;                 // fp32 product, like jnp.outer(f32)
    float sn, cs;
    sincosf(f, &sn, &cs);
    g_cos[i] = cs;
    g_sin[i] = sn;
}

// ==== GEMM: Y = X @ W, tf32 mma.sync, CTA 128x128, 8 warps x (64x32) ======
// 2 CTAs/SM (96KB smem, <=128 regs): barrier/memory bubbles of one CTA
// overlap with the co-resident CTA's MMA stream. grid 14x128 = 1792 CTAs.
#define BK 32
#define BM 128
#define BN 128
#define STAGES 3
#define A_FLOATS (BM * BK)                    // 4096
#define B_FLOATS (BN * BK)                    // 4096
#define STAGE_FLOATS (A_FLOATS + B_FLOATS)    // 8192
#define GEMM_SMEM (STAGES * STAGE_FLOATS * 4) // 98304
#define NCHUNK (D_IN / BK)                    // 64

__device__ __forceinline__ void cp16(float* smem, const float* g) {
    uint32_t s = (uint32_t)__cvta_generic_to_shared(smem);
    asm volatile("cp.async.cg.shared.global [%0], [%1], 16;" :: "r"(s), "l"(g));
}

__device__ __forceinline__ void load_chunk(float* st, int bm, int bn, int c, int tid) {
    const float* gA = g_X + (((size_t)(bm * 8)  * NKT + c * 4) << 7);
    const float* gB = g_W + (((size_t)(bn * 16) * NKT + c * 4) << 6);
#pragma unroll
    for (int j = 0; j < 4; j++) {                 // A: 1024 x 16B units
        int u = tid + j * 256;
        int seg = u >> 7, off = u & 127;          // seg = mt local (0..7)
        cp16(st + u * 4, gA + (size_t)seg * (NKT * 128) + off * 4);
    }
#pragma unroll
    for (int j = 0; j < 4; j++) {                 // B: 1024 x 16B units
        int u = tid + j * 256;
        int seg = u >> 6, off = u & 63;           // seg = nt local (0..15)
        cp16(st + A_FLOATS + u * 4, gB + (size_t)seg * (NKT * 64) + off * 4);
    }
}

__global__ __launch_bounds__(256, 2) void k_gemm() {
    extern __shared__ float sm[];
    const int tid = threadIdx.x;
    const int lane = tid & 31, wid = tid >> 5;
    const int bn = blockIdx.x, bm = blockIdx.y;
    const int wm = (wid & 1) << 6;    // 0 or 64
    const int wn = (wid >> 1) << 5;   // 0,32,64,96
    const int gp = lane >> 2, u = lane & 3;

    float acc[4][4][4];
#pragma unroll
    for (int a = 0; a < 4; a++)
#pragma unroll
        for (int b = 0; b < 4; b++)
#pragma unroll
            for (int c = 0; c < 4; c++) acc[a][b][c] = 0.f;

    // preload chunks 0,1
#pragma unroll
    for (int c = 0; c < 2; c++) {
        load_chunk(sm + c * STAGE_FLOATS, bm, bn, c, tid);
        asm volatile("cp.async.commit_group;");
    }

    const int mtl0 = wm >> 4;         // local m-tile base (0 or 4)
    const int ntl0 = wn >> 3;         // local n-tile base (0,4,8,12)

    for (int i = 0; i < NCHUNK; i++) {
        const int st = i % STAGES;
        if (i + 2 < NCHUNK) {
            load_chunk(sm + ((i + 2) % STAGES) * STAGE_FLOATS, bm, bn, i + 2, tid);
            asm volatile("cp.async.commit_group;");
            asm volatile("cp.async.wait_group 2;");
        } else {
            asm volatile("cp.async.wait_group 0;");
        }
        __syncthreads();

        const float* A  = sm + st * STAGE_FLOATS;
        const float* Bs = A + A_FLOATS;
#pragma unroll
        for (int ks = 0; ks < 4; ks++) {
            float4 afr[4];
            float2 bfr[4];
#pragma unroll
            for (int tm = 0; tm < 4; tm++)
                afr[tm] = *reinterpret_cast<const float4*>(
                    A + ((mtl0 + tm) * 4 + ks) * 128 + lane * 4);
#pragma unroll
            for (int tn = 0; tn < 4; tn++)
                bfr[tn] = *reinterpret_cast<const float2*>(
                    Bs + ((ntl0 + tn) * 4 + ks) * 64 + lane * 2);
#pragma unroll
            for (int tm = 0; tm < 4; tm++)
#pragma unroll
                for (int tn = 0; tn < 4; tn++) {
                    float* c = acc[tm][tn];
                    asm volatile(
                        "mma.sync.aligned.m16n8k8.row.col.f32.tf32.tf32.f32 "
                        "{%0,%1,%2,%3}, {%4,%5,%6,%7}, {%8,%9}, {%0,%1,%2,%3};"
                        : "+f"(c[0]), "+f"(c[1]), "+f"(c[2]), "+f"(c[3])
                        : "r"(__float_as_uint(afr[tm].x)), "r"(__float_as_uint(afr[tm].y)),
                          "r"(__float_as_uint(afr[tm].z)), "r"(__float_as_uint(afr[tm].w)),
                          "r"(__float_as_uint(bfr[tn].x)), "r"(__float_as_uint(bfr[tn].y)));
                }
        }
        __syncthreads();
    }

#pragma unroll
    for (int tm = 0; tm < 4; tm++) {
        int row0 = bm * BM + wm + tm * 16 + gp;
#pragma unroll
        for (int tn = 0; tn < 4; tn++) {
            int col = bn * BN + wn + tn * 8 + 2 * u;
            *reinterpret_cast<float2*>(&g_Y[(size_t)row0 * N_PAD + col]) =
                make_float2(acc[tm][tn][0], acc[tm][tn][1]);
            *reinterpret_cast<float2*>(&g_Y[(size_t)(row0 + 8) * N_PAD + col]) =
                make_float2(acc[tm][tn][2], acc[tm][tn][3]);
        }
    }
}

// ---------------- epilogue: rope + rank contraction, 4 tokens/CTA ----------
__global__ __launch_bounds__(512) void k_epi(float* __restrict__ out, int third) {
    __shared__ float sY[4][N_TOT];
    __shared__ float sBq[4][1024];
    __shared__ float sBk[4][256];
    const int g  = threadIdx.x >> 7;       // token group 0..3
    const int gt = threadIdx.x & 127;      // thread within group
    const int t  = blockIdx.x * 4 + g;     // token id
    const int s  = t & (SEQ - 1);          // position in sequence

    const float4* Yr4 = reinterpret_cast<const float4*>(g_Y + (size_t)t * N_PAD);
    for (int i = gt; i < N_TOT / 4; i += 128)
        reinterpret_cast<float4*>(sY[g])[i] = Yr4[i];
    __syncthreads();

#pragma unroll
    for (int p = gt; p < 512; p += 128) {
        int r = p >> 6, d = p & 63;
        float cs = g_cos[(s << 6) + d], sn = g_sin[(s << 6) + d];
        float x1 = sY[g][OFF_BQ + r * 128 + d];
        float x2 = sY[g][OFF_BQ + r * 128 + 64 + d];
        sBq[g][r * 128 + d]      = x1 * cs + x2 * sn;
        sBq[g][r * 128 + 64 + d] = x2 * cs - x1 * sn;
    }
    {
        int r = gt >> 6, d = gt & 63;
        float cs = g_cos[(s << 6) + d], sn = g_sin[(s << 6) + d];
        float x1 = sY[g][OFF_BK + r * 128 + d];
        float x2 = sY[g][OFF_BK + r * 128 + 64 + d];
        sBk[g][r * 128 + d]      = x1 * cs + x2 * sn;
        sBk[g][r * 128 + 64 + d] = x2 * cs - x1 * sn;
    }
    __syncthreads();

    const int d  = (gt & 63) * 2;
    const int h0 = gt >> 6;                // 0 or 1
    float* oq = out;
    float* ok = out + (size_t)third;
    float* ov = out + (size_t)2 * third;
    const size_t base = (size_t)t * 2048 + d;
    const float* sy = sY[g];
    const float* bq = sBq[g];
    const float* bk = sBk[g];
#pragma unroll
    for (int h = h0; h < 16; h += 2) {
        float qx = 0.f, qy = 0.f;
#pragma unroll
        for (int r = 0; r < 8; r++) {
            float a = sy[OFF_AQ + h * 8 + r];
            qx += a * bq[r * 128 + d];
            qy += a * bq[r * 128 + d + 1];
        }
        *reinterpret_cast<float2*>(&oq[base + h * 128]) =
            make_float2(qx * 0.125f, qy * 0.125f);
        float a0 = sy[OFF_AK + h * 2], a1 = sy[OFF_AK + h * 2 + 1];
        *reinterpret_cast<float2*>(&ok[base + h * 128]) = make_float2(
            (a0 * bk[d]     + a1 * bk[128 + d])     * 0.5f,
            (a0 * bk[d + 1] + a1 * bk[128 + d + 1]) * 0.5f);
        float b0 = sy[OFF_AV + h * 2], b1 = sy[OFF_AV + h * 2 + 1];
        *reinterpret_cast<float2*>(&ov[base + h * 128]) = make_float2(
            (b0 * sy[OFF_BV + d]     + b1 * sy[OFF_BV + 128 + d])     * 0.5f,
            (b0 * sy[OFF_BV + d + 1] + b1 * sy[OFF_BV + 128 + d + 1]) * 0.5f);
    }
}

extern "C" void kernel_launch(void* const* d_in, const int* in_sizes, int n_in,
                              void* d_out, int out_size) {
    const float* x    = (const float*)d_in[0];
    const float* wa_q = (const float*)d_in[1];
    const float* wa_k = (const float*)d_in[2];
    const float* wa_v = (const float*)d_in[3];
    const float* wb_q = (const float*)d_in[4];
    const float* wb_k = (const float*)d_in[5];
    const float* wb_v = (const float*)d_in[6];

    cudaFuncSetAttribute(k_gemm, cudaFuncAttributeMaxDynamicSharedMemorySize, GEMM_SMEM);

    k_prep_x<<<8192, 256>>>(x);
    dim3 wgrid(N_PAD / 32, D_IN / 32);
    k_prep_w<<<wgrid, dim3(32, 8)>>>(wa_q, wa_k, wa_v, wb_q, wb_k, wb_v);
    k_rope<<<(SEQ * 64 + 255) / 256, 256>>>();
    dim3 grid(N_PAD / BN, M_TOT / BM);
    k_gemm<<<grid, 256, GEMM_SMEM>>>();
    k_epi<<<M_TOT / 4, 512>>>((float*)d_out, out_size / 3);
}

// round 14
// speedup vs baseline: 1.0609x; 1.0609x over previous
#include <cuda_runtime.h>
#include <math.h>
#include <stdint.h>

#define M_TOT 16384
#define D_IN  2048
#define N_TOT 1728
#define N_PAD 1792
#define SEQ   4096
#define NKT   (D_IN / 8)      // 256 k-tiles of 8

// column offsets inside a packed Y row
#define OFF_AQ 0
#define OFF_AK 128
#define OFF_AV 160
#define OFF_BQ 192
#define OFF_BK 1216
#define OFF_BV 1472

// scratch (static device arrays: allocation-free per harness rules)
// A packed: [mt (m/16)][kt (k/8)][128 words]
__device__ float g_X[(size_t)M_TOT * D_IN];
// B packed: [nt (n/8)][kt (k/8)][64 words]   word = ((n&7)*4 + (k&3))*2 + ((k>>2)&1)
__device__ float g_W[(size_t)N_PAD * D_IN];
__device__ float g_Y[(size_t)M_TOT * N_PAD];
__device__ float g_cos[SEQ * 64];
__device__ float g_sin[SEQ * 64];

__device__ __forceinline__ float to_tf32(float x) {
    uint32_t r;
    asm("cvt.rna.tf32.f32 %0, %1;" : "=r"(r) : "f"(x));
    return __uint_as_float(r);
}

// pack X fragment-major with fully coalesced 128-bit loads & stores.
__global__ __launch_bounds__(256) void k_prep_x(const float* __restrict__ x) {
    int gid  = blockIdx.x * 256 + threadIdx.x;
    int lane = gid & 31;
    int w    = gid >> 5;               // warp id: 0..65535
    int gp   = lane & 7, ktl = lane >> 3;
    int kt   = (w & 63) * 4 + ktl;     // 0..255
    int mt   = w >> 6;                 // 0..1023
    const float* r0 = x + (size_t)(mt * 16 + gp) * D_IN + kt * 8;
    float4 a0 = *reinterpret_cast<const float4*>(r0);
    float4 a1 = *reinterpret_cast<const float4*>(r0 + 4);
    float4 b0 = *reinterpret_cast<const float4*>(r0 + 8 * D_IN);
    float4 b1 = *reinterpret_cast<const float4*>(r0 + 8 * D_IN + 4);
    a0.x = to_tf32(a0.x); a0.y = to_tf32(a0.y); a0.z = to_tf32(a0.z); a0.w = to_tf32(a0.w);
    a1.x = to_tf32(a1.x); a1.y = to_tf32(a1.y); a1.z = to_tf32(a1.z); a1.w = to_tf32(a1.w);
    b0.x = to_tf32(b0.x); b0.y = to_tf32(b0.y); b0.z = to_tf32(b0.z); b0.w = to_tf32(b0.w);
    b1.x = to_tf32(b1.x); b1.y = to_tf32(b1.y); b1.z = to_tf32(b1.z); b1.w = to_tf32(b1.w);
    float4* dst = reinterpret_cast<float4*>(
        g_X + (((size_t)mt * NKT + kt) << 7) + gp * 16);
    dst[0] = make_float4(a0.x, b0.x, a1.x, b1.x);
    dst[1] = make_float4(a0.y, b0.y, a1.y, b1.y);
    dst[2] = make_float4(a0.z, b0.z, a1.z, b1.z);
    dst[3] = make_float4(a0.w, b0.w, a1.w, b1.w);
}

// tiled transpose + pack into g_W fragment-major with 16B stores.
// Tile = 32 n x 32 k. Thread (tx=n_local, ty): kt_local = ty&3, half = ty>>2.
// For (n, kt) the 8 packed words are contiguous at (n&7)*8; word w <-> kk = (w&1)*4 + (w>>1).
__global__ void k_prep_w(
    const float* __restrict__ wa_q, const float* __restrict__ wa_k,
    const float* __restrict__ wa_v, const float* __restrict__ wb_q,
    const float* __restrict__ wb_k, const float* __restrict__ wb_v) {
    __shared__ float t[32][33];
    const int n0 = blockIdx.x * 32, k0 = blockIdx.y * 32;
    const int tx = threadIdx.x, ty = threadIdx.y;
    const float* src = nullptr; int ld = 0, nb = 0;
    if      (n0 < 128)  { src = wa_q; ld = 128;  nb = 0;    }
    else if (n0 < 160)  { src = wa_k; ld = 32;   nb = 128;  }
    else if (n0 < 192)  { src = wa_v; ld = 32;   nb = 160;  }
    else if (n0 < 1216) { src = wb_q; ld = 1024; nb = 192;  }
    else if (n0 < 1472) { src = wb_k; ld = 256;  nb = 1216; }
    else if (n0 < 1728) { src = wb_v; ld = 256;  nb = 1472; }
#pragma unroll
    for (int j = 0; j < 4; j++) {
        int r = ty + 8 * j;   // k row within tile (coalesced read along n)
        float v = src ? src[(size_t)(k0 + r) * ld + (n0 - nb) + tx] : 0.f;
        t[r][tx] = to_tf32(v);
    }
    __syncthreads();
    {
        const int n  = n0 + tx;
        const int ktl = ty & 3, half = ty >> 2;
        const int kt = (k0 >> 3) + ktl;
        const int kb = ktl * 8;           // k base within tile
        float v[4];
#pragma unroll
        for (int j = 0; j < 4; j++) {
            int w  = half * 4 + j;
            int kk = (w & 1) * 4 + (w >> 1);
            v[j] = t[kb + kk][tx];
        }
        float* dst = g_W + (((size_t)(n >> 3) * NKT + kt) << 6)
                         + (n & 7) * 8 + half * 4;
        *reinterpret_cast<float4*>(dst) = make_float4(v[0], v[1], v[2], v[3]);
    }
}

__global__ __launch_bounds__(256) void k_rope() {
    int i = blockIdx.x * 256 + threadIdx.x;
    if (i >= SEQ * 64) return;
    int s = i >> 6, d = i & 63;
    float ex   = -(float)d * (1.0f / 64.0f);
    float invf = exp2f(ex * 13.28771237954945f); // log2(10000)
    float f    = (float)s * invf;                 // fp32 product, like jnp.outer(f32)
    float sn, cs;
    sincosf(f, &sn, &cs);
    g_cos[i] = cs;
    g_sin[i] = sn;
}

// ==== GEMM: Y = X @ W, tf32 mma.sync, CTA 128x256, 8 warps x (64x64) ======
#define BK 32
#define BM 128
#define BN 256
#define STAGES 4
#define A_FLOATS (BM * BK)                    // 4096
#define STAGE_FLOATS ((BM + BN) * BK)         // 12288
#define GEMM_SMEM (STAGES * STAGE_FLOATS * 4) // 196608
#define NCHUNK (D_IN / BK)                    // 64

__device__ __forceinline__ void cp16(float* smem, const float* g) {
    uint32_t s = (uint32_t)__cvta_generic_to_shared(smem);
    asm volatile("cp.async.cg.shared.global [%0], [%1], 16;" :: "r"(s), "l"(g));
}

__device__ __forceinline__ void load_chunk(float* st, int bm, int bn, int c, int tid) {
    const float* gA = g_X + (((size_t)(bm * 8)  * NKT + c * 4) << 7);
    const float* gB = g_W + (((size_t)(bn * 32) * NKT + c * 4) << 6);
#pragma unroll
    for (int j = 0; j < 4; j++) {                 // A: 1024 x 16B units
        int u = tid + j * 256;
        int seg = u >> 7, off = u & 127;
        cp16(st + u * 4, gA + (size_t)seg * (NKT * 128) + off * 4);
    }
#pragma unroll
    for (int j = 0; j < 8; j++) {                 // B: 2048 x 16B units
        int u = tid + j * 256;
        int seg = u >> 6, off = u & 63;
        cp16(st + A_FLOATS + u * 4, gB + (size_t)seg * (NKT * 64) + off * 4);
    }
}

__global__ __launch_bounds__(256, 1) void k_gemm() {
    extern __shared__ float sm[];
    const int tid = threadIdx.x;
    const int lane = tid & 31, wid = tid >> 5;
    const int bn = blockIdx.x, bm = blockIdx.y;
    const int wm = (wid & 1) << 6;
    const int wn = (wid >> 1) << 6;
    const int gp = lane >> 2, u = lane & 3;

    float acc[4][8][4];
#pragma unroll
    for (int a = 0; a < 4; a++)
#pragma unroll
        for (int b = 0; b < 8; b++)
#pragma unroll
            for (int c = 0; c < 4; c++) acc[a][b][c] = 0.f;

#pragma unroll
    for (int c = 0; c < 2; c++) {
        load_chunk(sm + c * STAGE_FLOATS, bm, bn, c, tid);
        asm volatile("cp.async.commit_group;");
    }

    const int mtl0 = wm >> 4;
    const int ntl0 = wn >> 3;

    for (int i = 0; i < NCHUNK; i += 2) {
        if (i) __syncthreads();
        if (i + 2 < NCHUNK) {
            load_chunk(sm + ((i + 2) & 3) * STAGE_FLOATS, bm, bn, i + 2, tid);
            asm volatile("cp.async.commit_group;");
        }
        if (i + 3 < NCHUNK) {
            load_chunk(sm + ((i + 3) & 3) * STAGE_FLOATS, bm, bn, i + 3, tid);
            asm volatile("cp.async.commit_group;");
        }
        if (i + 2 < NCHUNK) asm volatile("cp.async.wait_group 2;");
        else                asm volatile("cp.async.wait_group 0;");
        __syncthreads();

#pragma unroll
        for (int half = 0; half < 2; half++) {
            const float* A  = sm + ((i + half) & 3) * STAGE_FLOATS;
            const float* Bs = A + A_FLOATS;
#pragma unroll
            for (int ks = 0; ks < 4; ks++) {
                float4 afr[4];
                float2 bfr[8];
#pragma unroll
                for (int tm = 0; tm < 4; tm++)
                    afr[tm] = *reinterpret_cast<const float4*>(
                        A + ((mtl0 + tm) * 4 + ks) * 128 + lane * 4);
#pragma unroll
                for (int tn = 0; tn < 8; tn++)
                    bfr[tn] = *reinterpret_cast<const float2*>(
                        Bs + ((ntl0 + tn) * 4 + ks) * 64 + lane * 2);
#pragma unroll
                for (int tm = 0; tm < 4; tm++)
#pragma unroll
                    for (int tn = 0; tn < 8; tn++) {
                        float* c = acc[tm][tn];
                        asm volatile(
                            "mma.sync.aligned.m16n8k8.row.col.f32.tf32.tf32.f32 "
                            "{%0,%1,%2,%3}, {%4,%5,%6,%7}, {%8,%9}, {%0,%1,%2,%3};"
                            : "+f"(c[0]), "+f"(c[1]), "+f"(c[2]), "+f"(c[3])
                            : "r"(__float_as_uint(afr[tm].x)), "r"(__float_as_uint(afr[tm].y)),
                              "r"(__float_as_uint(afr[tm].z)), "r"(__float_as_uint(afr[tm].w)),
                              "r"(__float_as_uint(bfr[tn].x)), "r"(__float_as_uint(bfr[tn].y)));
                    }
            }
        }
    }

#pragma unroll
    for (int tm = 0; tm < 4; tm++) {
        int row0 = bm * BM + wm + tm * 16 + gp;
#pragma unroll
        for (int tn = 0; tn < 8; tn++) {
            int col = bn * BN + wn + tn * 8 + 2 * u;
            *reinterpret_cast<float2*>(&g_Y[(size_t)row0 * N_PAD + col]) =
                make_float2(acc[tm][tn][0], acc[tm][tn][1]);
            *reinterpret_cast<float2*>(&g_Y[(size_t)(row0 + 8) * N_PAD + col]) =
                make_float2(acc[tm][tn][2], acc[tm][tn][3]);
        }
    }
}

// ---- epilogue: rope + rank contraction, 4 tokens/CTA, float4 stores -------
__global__ __launch_bounds__(512) void k_epi(float* __restrict__ out, int third) {
    __shared__ float sY[4][N_TOT];
    __shared__ float sBq[4][1024];
    __shared__ float sBk[4][256];
    const int g  = threadIdx.x >> 7;       // token group 0..3
    const int gt = threadIdx.x & 127;      // thread within group
    const int t  = blockIdx.x * 4 + g;     // token id
    const int s  = t & (SEQ - 1);          // position in sequence

    const float4* Yr4 = reinterpret_cast<const float4*>(g_Y + (size_t)t * N_PAD);
    for (int i = gt; i < N_TOT / 4; i += 128)
        reinterpret_cast<float4*>(sY[g])[i] = Yr4[i];
    __syncthreads();

#pragma unroll
    for (int p = gt; p < 512; p += 128) {
        int r = p >> 6, d = p & 63;
        float cs = g_cos[(s << 6) + d], sn = g_sin[(s << 6) + d];
        float x1 = sY[g][OFF_BQ + r * 128 + d];
        float x2 = sY[g][OFF_BQ + r * 128 + 64 + d];
        sBq[g][r * 128 + d]      = x1 * cs + x2 * sn;
        sBq[g][r * 128 + 64 + d] = x2 * cs - x1 * sn;
    }
    {
        int r = gt >> 6, d = gt & 63;
        float cs = g_cos[(s << 6) + d], sn = g_sin[(s << 6) + d];
        float x1 = sY[g][OFF_BK + r * 128 + d];
        float x2 = sY[g][OFF_BK + r * 128 + 64 + d];
        sBk[g][r * 128 + d]      = x1 * cs + x2 * sn;
        sBk[g][r * 128 + 64 + d] = x2 * cs - x1 * sn;
    }
    __syncthreads();

    // 4 adjacent d per thread, float4 loads/stores; h = hb + 4j covers 0..15
    const int d  = (gt & 31) * 4;
    const int hb = gt >> 5;                // 0..3
    float* oq = out;
    float* ok = out + (size_t)third;
    float* ov = out + (size_t)2 * third;
    const size_t base = (size_t)t * 2048 + d;
    const float* sy = sY[g];
    const float* bq = sBq[g];
    const float* bk = sBk[g];
    const float4 bv0 = *reinterpret_cast<const float4*>(sy + OFF_BV + d);
    const float4 bv1 = *reinterpret_cast<const float4*>(sy + OFF_BV + 128 + d);
    const float4 bk0 = *reinterpret_cast<const float4*>(bk + d);
    const float4 bk1 = *reinterpret_cast<const float4*>(bk + 128 + d);
#pragma unroll
    for (int j = 0; j < 4; j++) {
        const int h = hb + j * 4;
        float4 q = make_float4(0.f, 0.f, 0.f, 0.f);
#pragma unroll
        for (int r = 0; r < 8; r++) {
            float a = sy[OFF_AQ + h * 8 + r];
            float4 b = *reinterpret_cast<const float4*>(bq + r * 128 + d);
            q.x += a * b.x; q.y += a * b.y; q.z += a * b.z; q.w += a * b.w;
        }
        q.x *= 0.125f; q.y *= 0.125f; q.z *= 0.125f; q.w *= 0.125f;
        *reinterpret_cast<float4*>(&oq[base + h * 128]) = q;

        float a0 = sy[OFF_AK + h * 2] * 0.5f, a1 = sy[OFF_AK + h * 2 + 1] * 0.5f;
        *reinterpret_cast<float4*>(&ok[base + h * 128]) = make_float4(
            a0 * bk0.x + a1 * bk1.x, a0 * bk0.y + a1 * bk1.y,
            a0 * bk0.z + a1 * bk1.z, a0 * bk0.w + a1 * bk1.w);

        float b0 = sy[OFF_AV + h * 2] * 0.5f, b1 = sy[OFF_AV + h * 2 + 1] * 0.5f;
        *reinterpret_cast<float4*>(&ov[base + h * 128]) = make_float4(
            b0 * bv0.x + b1 * bv1.x, b0 * bv0.y + b1 * bv1.y,
            b0 * bv0.z + b1 * bv1.z, b0 * bv0.w + b1 * bv1.w);
    }
}

extern "C" void kernel_launch(void* const* d_in, const int* in_sizes, int n_in,
                              void* d_out, int out_size) {
    const float* x    = (const float*)d_in[0];
    const float* wa_q = (const float*)d_in[1];
    const float* wa_k = (const float*)d_in[2];
    const float* wa_v = (const float*)d_in[3];
    const float* wb_q = (const float*)d_in[4];
    const float* wb_k = (const float*)d_in[5];
    const float* wb_v = (const float*)d_in[6];

    cudaFuncSetAttribute(k_gemm, cudaFuncAttributeMaxDynamicSharedMemorySize, GEMM_SMEM);

    k_prep_x<<<8192, 256>>>(x);
    dim3 wgrid(N_PAD / 32, D_IN / 32);
    k_prep_w<<<wgrid, dim3(32, 8)>>>(wa_q, wa_k, wa_v, wb_q, wb_k, wb_v);
    k_rope<<<(SEQ * 64 + 255) / 256, 256>>>();
    dim3 grid(N_PAD / BN, M_TOT / BM);
    k_gemm<<<grid, 256, GEMM_SMEM>>>();
    k_epi<<<M_TOT / 4, 512>>>((float*)d_out, out_size / 3);
}

// round 15
// speedup vs baseline: 1.0629x; 1.0018x over previous
#include <cuda_runtime.h>
#include <math.h>
#include <stdint.h>

#define M_TOT 16384
#define D_IN  2048
#define N_TOT 1728
#define N_PAD 1792
#define SEQ   4096
#define NKT   (D_IN / 8)      // 256 k-tiles of 8

// column offsets inside a packed Y row
#define OFF_AQ 0
#define OFF_AK 128
#define OFF_AV 160
#define OFF_BQ 192
#define OFF_BK 1216
#define OFF_BV 1472

// scratch (static device arrays: allocation-free per harness rules)
// A packed: [mt (m/16)][kt (k/8)][128 words]
__device__ float g_X[(size_t)M_TOT * D_IN];
// B packed: [nt (n/8)][kt (k/8)][64 words]   word = ((n&7)*4 + (k&3))*2 + ((k>>2)&1)
__device__ float g_W[(size_t)N_PAD * D_IN];
__device__ float g_Y[(size_t)M_TOT * N_PAD];
__device__ float g_cos[SEQ * 64];
__device__ float g_sin[SEQ * 64];

__device__ __forceinline__ float to_tf32(float x) {
    uint32_t r;
    asm("cvt.rna.tf32.f32 %0, %1;" : "=r"(r) : "f"(x));
    return __uint_as_float(r);
}

// pack X fragment-major with fully coalesced 128-bit loads & stores.
__global__ __launch_bounds__(256) void k_prep_x(const float* __restrict__ x) {
    int gid  = blockIdx.x * 256 + threadIdx.x;
    int lane = gid & 31;
    int w    = gid >> 5;               // warp id: 0..65535
    int gp   = lane & 7, ktl = lane >> 3;
    int kt   = (w & 63) * 4 + ktl;     // 0..255
    int mt   = w >> 6;                 // 0..1023
    const float* r0 = x + (size_t)(mt * 16 + gp) * D_IN + kt * 8;
    float4 a0 = *reinterpret_cast<const float4*>(r0);
    float4 a1 = *reinterpret_cast<const float4*>(r0 + 4);
    float4 b0 = *reinterpret_cast<const float4*>(r0 + 8 * D_IN);
    float4 b1 = *reinterpret_cast<const float4*>(r0 + 8 * D_IN + 4);
    a0.x = to_tf32(a0.x); a0.y = to_tf32(a0.y); a0.z = to_tf32(a0.z); a0.w = to_tf32(a0.w);
    a1.x = to_tf32(a1.x); a1.y = to_tf32(a1.y); a1.z = to_tf32(a1.z); a1.w = to_tf32(a1.w);
    b0.x = to_tf32(b0.x); b0.y = to_tf32(b0.y); b0.z = to_tf32(b0.z); b0.w = to_tf32(b0.w);
    b1.x = to_tf32(b1.x); b1.y = to_tf32(b1.y); b1.z = to_tf32(b1.z); b1.w = to_tf32(b1.w);
    float4* dst = reinterpret_cast<float4*>(
        g_X + (((size_t)mt * NKT + kt) << 7) + gp * 16);
    dst[0] = make_float4(a0.x, b0.x, a1.x, b1.x);
    dst[1] = make_float4(a0.y, b0.y, a1.y, b1.y);
    dst[2] = make_float4(a0.z, b0.z, a1.z, b1.z);
    dst[3] = make_float4(a0.w, b0.w, a1.w, b1.w);
}

// tiled transpose + pack into g_W fragment-major with 16B stores.
__global__ void k_prep_w(
    const float* __restrict__ wa_q, const float* __restrict__ wa_k,
    const float* __restrict__ wa_v, const float* __restrict__ wb_q,
    const float* __restrict__ wb_k, const float* __restrict__ wb_v) {
    __shared__ float t[32][33];
    const int n0 = blockIdx.x * 32, k0 = blockIdx.y * 32;
    const int tx = threadIdx.x, ty = threadIdx.y;
    const float* src = nullptr; int ld = 0, nb = 0;
    if      (n0 < 128)  { src = wa_q; ld = 128;  nb = 0;    }
    else if (n0 < 160)  { src = wa_k; ld = 32;   nb = 128;  }
    else if (n0 < 192)  { src = wa_v; ld = 32;   nb = 160;  }
    else if (n0 < 1216) { src = wb_q; ld = 1024; nb = 192;  }
    else if (n0 < 1472) { src = wb_k; ld = 256;  nb = 1216; }
    else if (n0 < 1728) { src = wb_v; ld = 256;  nb = 1472; }
#pragma unroll
    for (int j = 0; j < 4; j++) {
        int r = ty + 8 * j;   // k row within tile (coalesced read along n)
        float v = src ? src[(size_t)(k0 + r) * ld + (n0 - nb) + tx] : 0.f;
        t[r][tx] = to_tf32(v);
    }
    __syncthreads();
    {
        const int n  = n0 + tx;
        const int ktl = ty & 3, half = ty >> 2;
        const int kt = (k0 >> 3) + ktl;
        const int kb = ktl * 8;           // k base within tile
        float v[4];
#pragma unroll
        for (int j = 0; j < 4; j++) {
            int w  = half * 4 + j;
            int kk = (w & 1) * 4 + (w >> 1);
            v[j] = t[kb + kk][tx];
        }
        float* dst = g_W + (((size_t)(n >> 3) * NKT + kt) << 6)
                         + (n & 7) * 8 + half * 4;
        *reinterpret_cast<float4*>(dst) = make_float4(v[0], v[1], v[2], v[3]);
    }
}

__global__ __launch_bounds__(256) void k_rope() {
    int i = blockIdx.x * 256 + threadIdx.x;
    if (i >= SEQ * 64) return;
    int s = i >> 6, d = i & 63;
    float ex   = -(float)d * (1.0f / 64.0f);
    float invf = exp2f(ex * 13.28771237954945f); // log2(10000)
    float f    = (float)s * invf;                 // fp32 product, like jnp.outer(f32)
    float sn, cs;
    sincosf(f, &sn, &cs);
    g_cos[i] = cs;
    g_sin[i] = sn;
}

// ==== GEMM: Y = X @ W, tf32 mma.sync, CTA 128x256, 8 warps x (64x64) ======
// 4 stages, 2 chunks per barrier pair, fragments double-buffered across the
// 8 ks-steps of each barrier block.
#define BK 32
#define BM 128
#define BN 256
#define STAGES 4
#define A_FLOATS (BM * BK)                    // 4096
#define STAGE_FLOATS ((BM + BN) * BK)         // 12288
#define GEMM_SMEM (STAGES * STAGE_FLOATS * 4) // 196608
#define NCHUNK (D_IN / BK)                    // 64

__device__ __forceinline__ void cp16(float* smem, const float* g) {
    uint32_t s = (uint32_t)__cvta_generic_to_shared(smem);
    asm volatile("cp.async.cg.shared.global [%0], [%1], 16;" :: "r"(s), "l"(g));
}

__device__ __forceinline__ void load_chunk(float* st, int bm, int bn, int c, int tid) {
    const float* gA = g_X + (((size_t)(bm * 8)  * NKT + c * 4) << 7);
    const float* gB = g_W + (((size_t)(bn * 32) * NKT + c * 4) << 6);
#pragma unroll
    for (int j = 0; j < 4; j++) {                 // A: 1024 x 16B units
        int u = tid + j * 256;
        int seg = u >> 7, off = u & 127;
        cp16(st + u * 4, gA + (size_t)seg * (NKT * 128) + off * 4);
    }
#pragma unroll
    for (int j = 0; j < 8; j++) {                 // B: 2048 x 16B units
        int u = tid + j * 256;
        int seg = u >> 6, off = u & 63;
        cp16(st + A_FLOATS + u * 4, gB + (size_t)seg * (NKT * 64) + off * 4);
    }
}

__device__ __forceinline__ void load_frags(float4 afr[4], float2 bfr[8],
                                           const float* A, int mtl0, int ntl0,
                                           int ks, int lane) {
    const float* Bs = A + A_FLOATS;
#pragma unroll
    for (int tm = 0; tm < 4; tm++)
        afr[tm] = *reinterpret_cast<const float4*>(
            A + ((mtl0 + tm) * 4 + ks) * 128 + lane * 4);
#pragma unroll
    for (int tn = 0; tn < 8; tn++)
        bfr[tn] = *reinterpret_cast<const float2*>(
            Bs + ((ntl0 + tn) * 4 + ks) * 64 + lane * 2);
}

__global__ __launch_bounds__(256, 1) void k_gemm() {
    extern __shared__ float sm[];
    const int tid = threadIdx.x;
    const int lane = tid & 31, wid = tid >> 5;
    const int bn = blockIdx.x, bm = blockIdx.y;
    const int wm = (wid & 1) << 6;
    const int wn = (wid >> 1) << 6;
    const int gp = lane >> 2, u = lane & 3;

    float acc[4][8][4];
#pragma unroll
    for (int a = 0; a < 4; a++)
#pragma unroll
        for (int b = 0; b < 8; b++)
#pragma unroll
            for (int c = 0; c < 4; c++) acc[a][b][c] = 0.f;

#pragma unroll
    for (int c = 0; c < 2; c++) {
        load_chunk(sm + c * STAGE_FLOATS, bm, bn, c, tid);
        asm volatile("cp.async.commit_group;");
    }

    const int mtl0 = wm >> 4;
    const int ntl0 = wn >> 3;

    for (int i = 0; i < NCHUNK; i += 2) {
        if (i) __syncthreads();
        if (i + 2 < NCHUNK) {
            load_chunk(sm + ((i + 2) & 3) * STAGE_FLOATS, bm, bn, i + 2, tid);
            asm volatile("cp.async.commit_group;");
        }
        if (i + 3 < NCHUNK) {
            load_chunk(sm + ((i + 3) & 3) * STAGE_FLOATS, bm, bn, i + 3, tid);
            asm volatile("cp.async.commit_group;");
        }
        if (i + 2 < NCHUNK) asm volatile("cp.async.wait_group 2;");
        else                asm volatile("cp.async.wait_group 0;");
        __syncthreads();

        const float* Ah0 = sm + (i & 3) * STAGE_FLOATS;
        const float* Ah1 = sm + ((i + 1) & 3) * STAGE_FLOATS;

        float4 afr[2][4];
        float2 bfr[2][8];
        load_frags(afr[0], bfr[0], Ah0, mtl0, ntl0, 0, lane);

#pragma unroll
        for (int s2 = 0; s2 < 8; s2++) {
            const int cur = s2 & 1;
            if (s2 < 7) {
                const float* An = ((s2 + 1) & 4) ? Ah1 : Ah0;
                load_frags(afr[cur ^ 1], bfr[cur ^ 1], An, mtl0, ntl0,
                           (s2 + 1) & 3, lane);
            }
#pragma unroll
            for (int tm = 0; tm < 4; tm++)
#pragma unroll
                for (int tn = 0; tn < 8; tn++) {
                    float* c = acc[tm][tn];
                    asm volatile(
                        "mma.sync.aligned.m16n8k8.row.col.f32.tf32.tf32.f32 "
                        "{%0,%1,%2,%3}, {%4,%5,%6,%7}, {%8,%9}, {%0,%1,%2,%3};"
                        : "+f"(c[0]), "+f"(c[1]), "+f"(c[2]), "+f"(c[3])
                        : "r"(__float_as_uint(afr[cur][tm].x)),
                          "r"(__float_as_uint(afr[cur][tm].y)),
                          "r"(__float_as_uint(afr[cur][tm].z)),
                          "r"(__float_as_uint(afr[cur][tm].w)),
                          "r"(__float_as_uint(bfr[cur][tn].x)),
                          "r"(__float_as_uint(bfr[cur][tn].y)));
                }
        }
    }

#pragma unroll
    for (int tm = 0; tm < 4; tm++) {
        int row0 = bm * BM + wm + tm * 16 + gp;
#pragma unroll
        for (int tn = 0; tn < 8; tn++) {
            int col = bn * BN + wn + tn * 8 + 2 * u;
            *reinterpret_cast<float2*>(&g_Y[(size_t)row0 * N_PAD + col]) =
                make_float2(acc[tm][tn][0], acc[tm][tn][1]);
            *reinterpret_cast<float2*>(&g_Y[(size_t)(row0 + 8) * N_PAD + col]) =
                make_float2(acc[tm][tn][2], acc[tm][tn][3]);
        }
    }
}

// ---- epilogue: rope + rank contraction, 4 tokens/CTA, float4 stores -------
__global__ __launch_bounds__(512) void k_epi(float* __restrict__ out, int third) {
    __shared__ float sY[4][N_TOT];
    __shared__ float sBq[4][1024];
    __shared__ float sBk[4][256];
    const int g  = threadIdx.x >> 7;       // token group 0..3
    const int gt = threadIdx.x & 127;      // thread within group
    const int t  = blockIdx.x * 4 + g;     // token id
    const int s  = t & (SEQ - 1);          // position in sequence

    const float4* Yr4 = reinterpret_cast<const float4*>(g_Y + (size_t)t * N_PAD);
    for (int i = gt; i < N_TOT / 4; i += 128)
        reinterpret_cast<float4*>(sY[g])[i] = Yr4[i];
    __syncthreads();

#pragma unroll
    for (int p = gt; p < 512; p += 128) {
        int r = p >> 6, d = p & 63;
        float cs = g_cos[(s << 6) + d], sn = g_sin[(s << 6) + d];
        float x1 = sY[g][OFF_BQ + r * 128 + d];
        float x2 = sY[g][OFF_BQ + r * 128 + 64 + d];
        sBq[g][r * 128 + d]      = x1 * cs + x2 * sn;
        sBq[g][r * 128 + 64 + d] = x2 * cs - x1 * sn;
    }
    {
        int r = gt >> 6, d = gt & 63;
        float cs = g_cos[(s << 6) + d], sn = g_sin[(s << 6) + d];
        float x1 = sY[g][OFF_BK + r * 128 + d];
        float x2 = sY[g][OFF_BK + r * 128 + 64 + d];
        sBk[g][r * 128 + d]      = x1 * cs + x2 * sn;
        sBk[g][r * 128 + 64 + d] = x2 * cs - x1 * sn;
    }
    __syncthreads();

    const int d  = (gt & 31) * 4;
    const int hb = gt >> 5;                // 0..3
    float* oq = out;
    float* ok = out + (size_t)third;
    float* ov = out + (size_t)2 * third;
    const size_t base = (size_t)t * 2048 + d;
    const float* sy = sY[g];
    const float* bq = sBq[g];
    const float* bk = sBk[g];
    const float4 bv0 = *reinterpret_cast<const float4*>(sy + OFF_BV + d);
    const float4 bv1 = *reinterpret_cast<const float4*>(sy + OFF_BV + 128 + d);
    const float4 bk0 = *reinterpret_cast<const float4*>(bk + d);
    const float4 bk1 = *reinterpret_cast<const float4*>(bk + 128 + d);
#pragma unroll
    for (int j = 0; j < 4; j++) {
        const int h = hb + j * 4;
        float4 q = make_float4(0.f, 0.f, 0.f, 0.f);
#pragma unroll
        for (int r = 0; r < 8; r++) {
            float a = sy[OFF_AQ + h * 8 + r];
            float4 b = *reinterpret_cast<const float4*>(bq + r * 128 + d);
            q.x += a * b.x; q.y += a * b.y; q.z += a * b.z; q.w += a * b.w;
        }
        q.x *= 0.125f; q.y *= 0.125f; q.z *= 0.125f; q.w *= 0.125f;
        *reinterpret_cast<float4*>(&oq[base + h * 128]) = q;

        float a0 = sy[OFF_AK + h * 2] * 0.5f, a1 = sy[OFF_AK + h * 2 + 1] * 0.5f;
        *reinterpret_cast<float4*>(&ok[base + h * 128]) = make_float4(
            a0 * bk0.x + a1 * bk1.x, a0 * bk0.y + a1 * bk1.y,
            a0 * bk0.z + a1 * bk1.z, a0 * bk0.w + a1 * bk1.w);

        float b0 = sy[OFF_AV + h * 2] * 0.5f, b1 = sy[OFF_AV + h * 2 + 1] * 0.5f;
        *reinterpret_cast<float4*>(&ov[base + h * 128]) = make_float4(
            b0 * bv0.x + b1 * bv1.x, b0 * bv0.y + b1 * bv1.y,
            b0 * bv0.z + b1 * bv1.z, b0 * bv0.w + b1 * bv1.w);
    }
}

extern "C" void kernel_launch(void* const* d_in, const int* in_sizes, int n_in,
                              void* d_out, int out_size) {
    const float* x    = (const float*)d_in[0];
    const float* wa_q = (const float*)d_in[1];
    const float* wa_k = (const float*)d_in[2];
    const float* wa_v = (const float*)d_in[3];
    const float* wb_q = (const float*)d_in[4];
    const float* wb_k = (const float*)d_in[5];
    const float* wb_v = (const float*)d_in[6];

    cudaFuncSetAttribute(k_gemm, cudaFuncAttributeMaxDynamicSharedMemorySize, GEMM_SMEM);

    k_prep_x<<<8192, 256>>>(x);
    dim3 wgrid(N_PAD / 32, D_IN / 32);
    k_prep_w<<<wgrid, dim3(32, 8)>>>(wa_q, wa_k, wa_v, wb_q, wb_k, wb_v);
    k_rope<<<(SEQ * 64 + 255) / 256, 256>>>();
    dim3 grid(N_PAD / BN, M_TOT / BM);
    k_gemm<<<grid, 256, GEMM_SMEM>>>();
    k_epi<<<M_TOT / 4, 512>>>((float*)d_out, out_size / 3);
}